// round 4
// baseline (speedup 1.0000x reference)
#include <cuda_runtime.h>
#include <math.h>

#define N_NODES 50000
#define N_EDGES 640000
#define F 128
#define F4 32            // F/4
#define NCLASS 40

// ---------------- scratch (static __device__, no allocation) ----------------
__device__ float4 g_h [N_NODES * F4];   // GEMM output (h = x @ W)
__device__ float4 g_xa[N_NODES * F4];   // activations ping
__device__ float4 g_xb[N_NODES * F4];   // activations pong
__device__ int    g_cnt[N_NODES];
__device__ int    g_off[N_NODES + 1];
__device__ int    g_cur[N_NODES];
__device__ int    g_srcs[N_EDGES];

// ---------------- CSR build ----------------
__global__ void zero_cnt_kernel() {
    int i = blockIdx.x * blockDim.x + threadIdx.x;
    if (i < N_NODES) g_cnt[i] = 0;
}

__global__ void hist_kernel(const int* __restrict__ dst) {
    int e = blockIdx.x * blockDim.x + threadIdx.x;
    if (e < N_EDGES) atomicAdd(&g_cnt[dst[e]], 1);
}

// single-block exclusive scan over 50000 counts
__global__ void scan_kernel() {
    __shared__ int sh[1024];
    __shared__ int carry;
    if (threadIdx.x == 0) carry = 0;
    __syncthreads();
    for (int base = 0; base < N_NODES; base += 1024) {
        int i = base + threadIdx.x;
        int v = (i < N_NODES) ? g_cnt[i] : 0;
        sh[threadIdx.x] = v;
        __syncthreads();
        for (int off = 1; off < 1024; off <<= 1) {
            int t = (threadIdx.x >= off) ? sh[threadIdx.x - off] : 0;
            __syncthreads();
            sh[threadIdx.x] += t;
            __syncthreads();
        }
        int incl = sh[threadIdx.x];
        int excl = carry + incl - v;
        if (i < N_NODES) { g_off[i] = excl; g_cur[i] = excl; }
        __syncthreads();
        if (threadIdx.x == 0) carry += sh[1023];
        __syncthreads();
    }
    if (threadIdx.x == 0) g_off[N_NODES] = carry;  // == N_EDGES
}

__global__ void fill_kernel(const int* __restrict__ src,
                            const int* __restrict__ dst) {
    int e = blockIdx.x * blockDim.x + threadIdx.x;
    if (e < N_EDGES) {
        int d = dst[e];
        int p = atomicAdd(&g_cur[d], 1);
        g_srcs[p] = src[e];
    }
}

// ---------------- GEMM: g_h[n,128] = IN[n,128] @ W[128,128] ----------------
// IN chosen at COMPILE TIME: 0 = external param, 1 = g_xa, 2 = g_xb.
// 64 rows/block, 256 threads, micro-tile 8 rows x 4 cols, K tiled by 32.
#define GM 64
template<int SEL>
__global__ void gemm128_kernel(const float4* __restrict__ Xext,
                               const float* __restrict__ W, int nrows) {
    __shared__ float  xs[GM][33];
    __shared__ float4 ws[32][32];
    const int tid = threadIdx.x;
    const int tx = tid & 31;
    const int ty = tid >> 5;
    const int row0 = blockIdx.x * GM;
    const float4* W4 = (const float4*)W;

    float4 acc[8];
    #pragma unroll
    for (int j = 0; j < 8; j++) acc[j] = make_float4(0.f, 0.f, 0.f, 0.f);

    for (int kk = 0; kk < 4; kk++) {
        // load X tile: 64 rows x 8 float4 (32 cols)
        for (int i = tid; i < GM * 8; i += 256) {
            int r = i >> 3, c = i & 7;
            int gr = row0 + r;
            float4 v = make_float4(0.f, 0.f, 0.f, 0.f);
            if (gr < nrows) {
                if (SEL == 0)      v = Xext[gr * F4 + kk * 8 + c];
                else if (SEL == 1) v = g_xa[gr * F4 + kk * 8 + c];
                else               v = g_xb[gr * F4 + kk * 8 + c];
            }
            xs[r][c * 4 + 0] = v.x;
            xs[r][c * 4 + 1] = v.y;
            xs[r][c * 4 + 2] = v.z;
            xs[r][c * 4 + 3] = v.w;
        }
        // load W tile: 32 k x 128 cols (32 float4)
        for (int i = tid; i < 32 * 32; i += 256) {
            int k = i >> 5, c4 = i & 31;
            ws[k][c4] = W4[(kk * 32 + k) * 32 + c4];
        }
        __syncthreads();
        #pragma unroll
        for (int k = 0; k < 32; k++) {
            float4 b4 = ws[k][tx];
            #pragma unroll
            for (int j = 0; j < 8; j++) {
                float a = xs[ty * 8 + j][k];
                acc[j].x += a * b4.x;
                acc[j].y += a * b4.y;
                acc[j].z += a * b4.z;
                acc[j].w += a * b4.w;
            }
        }
        __syncthreads();
    }
    #pragma unroll
    for (int j = 0; j < 8; j++) {
        int gr = row0 + ty * 8 + j;
        if (gr < nrows) g_h[gr * F4 + tx] = acc[j];
    }
}

// ---------------- aggregate + bias + L2 normalize + ReLU ----------------
// reads g_h; OUT chosen at COMPILE TIME: 0 = external param, 1 = g_xa, 2 = g_xb.
// one warp per node; lane owns 4 contiguous features
template<int SEL>
__global__ void agg_norm_relu_kernel(const float* __restrict__ bias,
                                     float4* __restrict__ OUText) {
    int node = (blockIdx.x * blockDim.x + threadIdx.x) >> 5;
    int lane = threadIdx.x & 31;
    if (node >= N_NODES) return;
    int s = g_off[node], e = g_off[node + 1];
    float4 acc = make_float4(0.f, 0.f, 0.f, 0.f);
    for (int i = s; i < e; i++) {
        int u = g_srcs[i];
        float4 v = g_h[u * F4 + lane];
        acc.x += v.x; acc.y += v.y; acc.z += v.z; acc.w += v.w;
    }
    float4 b4 = ((const float4*)bias)[lane];
    acc.x += b4.x; acc.y += b4.y; acc.z += b4.z; acc.w += b4.w;
    float ss = acc.x * acc.x + acc.y * acc.y + acc.z * acc.z + acc.w * acc.w;
    #pragma unroll
    for (int off = 16; off > 0; off >>= 1)
        ss += __shfl_xor_sync(0xFFFFFFFFu, ss, off);
    float inv = 1.f / fmaxf(sqrtf(ss), 1e-12f);
    float4 r;
    r.x = fmaxf(acc.x * inv, 0.f);
    r.y = fmaxf(acc.y * inv, 0.f);
    r.z = fmaxf(acc.z * inv, 0.f);
    r.w = fmaxf(acc.w * inv, 0.f);
    if (SEL == 0)      OUText[node * F4 + lane] = r;
    else if (SEL == 1) g_xa[node * F4 + lane]   = r;
    else               g_xb[node * F4 + lane]   = r;
}

// ---------------- final linear + softmax ----------------
__global__ void final_kernel(const float* __restrict__ X4,
                             const float* __restrict__ Wl,
                             const float* __restrict__ bl,
                             float* __restrict__ logits,
                             float* __restrict__ probs) {
    __shared__ float xsh[32][129];
    __shared__ float wsh[F][NCLASS];
    __shared__ float lsh[32][NCLASS];
    __shared__ float mx[32], inv[32];
    int tid = threadIdx.x;
    int n0 = blockIdx.x * 32;

    for (int i = tid; i < 32 * F; i += 256) {
        int n = i >> 7, k = i & 127;
        int gn = n0 + n;
        xsh[n][k] = (gn < N_NODES) ? X4[gn * F + k] : 0.f;
    }
    for (int i = tid; i < F * NCLASS; i += 256)
        wsh[i / NCLASS][i % NCLASS] = Wl[i];
    __syncthreads();

    for (int idx = tid; idx < 32 * NCLASS; idx += 256) {
        int n = idx / NCLASS, c = idx % NCLASS;
        float s = bl[c];
        #pragma unroll
        for (int k = 0; k < F; k++) s += xsh[n][k] * wsh[k][c];
        lsh[n][c] = s;
    }
    __syncthreads();

    if (tid < 32) {
        float m = -1e30f;
        #pragma unroll
        for (int c = 0; c < NCLASS; c++) m = fmaxf(m, lsh[tid][c]);
        float sum = 0.f;
        #pragma unroll
        for (int c = 0; c < NCLASS; c++) sum += expf(lsh[tid][c] - m);
        mx[tid] = m; inv[tid] = 1.f / sum;
    }
    __syncthreads();

    for (int idx = tid; idx < 32 * NCLASS; idx += 256) {
        int n = idx / NCLASS, c = idx % NCLASS;
        int gn = n0 + n;
        if (gn < N_NODES) {
            float l = lsh[n][c];
            logits[gn * NCLASS + c] = l;
            probs[gn * NCLASS + c]  = expf(l - mx[n]) * inv[n];
        }
    }
}

// ---------------- launch ----------------
extern "C" void kernel_launch(void* const* d_in, const int* in_sizes, int n_in,
                              void* d_out, int out_size) {
    const float* x  = (const float*)d_in[0];
    const int*   ei = (const int*)d_in[1];   // int32 (2, 640000) — JAX x64 disabled!
    const float* W1 = (const float*)d_in[2];
    const float* b1 = (const float*)d_in[3];
    const float* W2 = (const float*)d_in[4];
    const float* b2 = (const float*)d_in[5];
    const float* W3 = (const float*)d_in[6];
    const float* b3 = (const float*)d_in[7];
    const float* W4 = (const float*)d_in[8];
    const float* b4 = (const float*)d_in[9];
    const float* Wl = (const float*)d_in[10];
    const float* bl = (const float*)d_in[11];

    const int* src = ei;
    const int* dst = ei + N_EDGES;

    float* out    = (float*)d_out;
    float* logits = out;                          // 50000*40
    float* probs  = out + N_NODES * NCLASS;       // 50000*40
    float* x4out  = out + 2 * N_NODES * NCLASS;   // 50000*128 (16B-aligned offset)

    const int T = 256;
    const int gemm_blocks = (N_NODES + GM - 1) / GM;        // 782
    const int agg_blocks  = (N_NODES * 32 + T - 1) / T;     // 6250
    const int edge_blocks = (N_EDGES + T - 1) / T;          // 2500

    // Build CSR once per call (reused by all 4 layers)
    zero_cnt_kernel<<<(N_NODES + T - 1) / T, T>>>();
    hist_kernel<<<edge_blocks, T>>>(dst);
    scan_kernel<<<1, 1024>>>();
    fill_kernel<<<edge_blocks, T>>>(src, dst);

    // layer 1: x -> g_h -> g_xa
    gemm128_kernel<0><<<gemm_blocks, T>>>((const float4*)x, W1, N_NODES);
    agg_norm_relu_kernel<1><<<agg_blocks, T>>>(b1, nullptr);
    // layer 2: g_xa -> g_h -> g_xb
    gemm128_kernel<1><<<gemm_blocks, T>>>(nullptr, W2, N_NODES);
    agg_norm_relu_kernel<2><<<agg_blocks, T>>>(b2, nullptr);
    // layer 3: g_xb -> g_h -> g_xa
    gemm128_kernel<2><<<gemm_blocks, T>>>(nullptr, W3, N_NODES);
    agg_norm_relu_kernel<1><<<agg_blocks, T>>>(b3, nullptr);
    // layer 4: g_xa -> g_h -> x4out (external)
    gemm128_kernel<1><<<gemm_blocks, T>>>(nullptr, W4, N_NODES);
    agg_norm_relu_kernel<0><<<agg_blocks, T>>>(b4, (float4*)x4out);

    // head: logits + softmax
    final_kernel<<<(N_NODES + 31) / 32, T>>>(x4out, Wl, bl, logits, probs);
}

// round 5
// speedup vs baseline: 1.1463x; 1.1463x over previous
#include <cuda_runtime.h>
#include <math.h>

#define N_NODES 50000
#define N_EDGES 640000
#define F 128
#define F4 32            // F/4
#define NCLASS 40
#define SCAN_BLKS 49     // 49*1024 = 50176 >= N_NODES

// ---------------- scratch (static __device__, no allocation) ----------------
__device__ float4 g_h [N_NODES * F4];   // GEMM output (h = x @ W)
__device__ float4 g_xa[N_NODES * F4];   // activations ping
__device__ float4 g_xb[N_NODES * F4];   // activations pong
__device__ int    g_cnt[N_NODES];
__device__ int    g_off[N_NODES + 1];
__device__ int    g_cur[N_NODES];
__device__ int    g_srcs[N_EDGES];
__device__ int    g_bsum[64];
__device__ int    g_bpre[64];

// ---------------- CSR build ----------------
__global__ void zero_cnt_kernel() {
    int i = blockIdx.x * blockDim.x + threadIdx.x;
    if (i < N_NODES) g_cnt[i] = 0;
}

__global__ void hist_kernel(const int* __restrict__ dst) {
    int e = blockIdx.x * blockDim.x + threadIdx.x;
    if (e < N_EDGES) atomicAdd(&g_cnt[dst[e]], 1);
}

// phase A: per-block local exclusive scan (1024 elems/block), block sums out
__global__ void scanA_kernel() {
    __shared__ int sh[1024];
    int tid = threadIdx.x;
    int i = blockIdx.x * 1024 + tid;
    int v = (i < N_NODES) ? g_cnt[i] : 0;
    sh[tid] = v;
    __syncthreads();
    for (int off = 1; off < 1024; off <<= 1) {
        int t = (tid >= off) ? sh[tid - off] : 0;
        __syncthreads();
        sh[tid] += t;
        __syncthreads();
    }
    if (i < N_NODES) g_off[i] = sh[tid] - v;   // local exclusive
    if (tid == 1023) g_bsum[blockIdx.x] = sh[1023];
}

// phase B: exclusive scan of 49 block sums (single 64-thread block)
__global__ void scanB_kernel() {
    __shared__ int sh[64];
    int tid = threadIdx.x;
    int v = (tid < SCAN_BLKS) ? g_bsum[tid] : 0;
    sh[tid] = v;
    __syncthreads();
    for (int off = 1; off < 64; off <<= 1) {
        int t = (tid >= off) ? sh[tid - off] : 0;
        __syncthreads();
        sh[tid] += t;
        __syncthreads();
    }
    if (tid < SCAN_BLKS) g_bpre[tid] = sh[tid] - v;
    if (tid == 63) g_off[N_NODES] = sh[63];    // total == N_EDGES
}

// phase C: add block prefix, init cursors
__global__ void scanC_kernel() {
    int i = blockIdx.x * 1024 + threadIdx.x;
    if (i < N_NODES) {
        int o = g_off[i] + g_bpre[blockIdx.x];
        g_off[i] = o;
        g_cur[i] = o;
    }
}

__global__ void fill_kernel(const int* __restrict__ src,
                            const int* __restrict__ dst) {
    int e = blockIdx.x * blockDim.x + threadIdx.x;
    if (e < N_EDGES) {
        int d = dst[e];
        int p = atomicAdd(&g_cur[d], 1);
        g_srcs[p] = src[e];
    }
}

// ---------------- GEMM v2: g_h[n,128] = IN[n,128] @ W[128,128] ----------------
// 128 rows/block, 256 threads, 8x8 micro-tile, W fully smem-resident.
// IN chosen at COMPILE TIME: 0 = external param, 1 = g_xa, 2 = g_xb.
#define WS_LD 132                 // W row pitch (floats), 16B-aligned, conflict-free
#define XS_LD 33                  // X row pitch (floats)
#define GEMM_SMEM ((128 * WS_LD + 128 * XS_LD) * 4)

template<int SEL>
__global__ __launch_bounds__(256, 2)
void gemm128_kernel(const float4* __restrict__ Xext,
                    const float* __restrict__ W, int nrows) {
    extern __shared__ float smem_g[];
    float* ws = smem_g;               // [128][132]
    float* xs = smem_g + 128 * WS_LD; // [128][33]
    const int tid = threadIdx.x;
    const int c0 = (tid & 15) * 4;    // cols {c0..c0+3, c0+64..c0+67}
    const int ty = tid >> 4;          // rows ty*8 .. ty*8+7
    const int row0 = blockIdx.x * 128;
    const float4* W4 = (const float4*)W;

    // load W (128x128) once
    for (int i = tid; i < 128 * 32; i += 256) {
        int k = i >> 5, c4 = i & 31;
        float4 w = W4[k * 32 + c4];
        float* p = ws + k * WS_LD + c4 * 4;
        p[0] = w.x; p[1] = w.y; p[2] = w.z; p[3] = w.w;
    }

    float4 acc0[8], acc1[8];
    #pragma unroll
    for (int j = 0; j < 8; j++) {
        acc0[j] = make_float4(0.f, 0.f, 0.f, 0.f);
        acc1[j] = make_float4(0.f, 0.f, 0.f, 0.f);
    }

    for (int kk = 0; kk < 4; kk++) {
        // load X tile: 128 rows x 32 cols
        for (int i = tid; i < 128 * 8; i += 256) {
            int r = i >> 3, c = i & 7;
            int gr = row0 + r;
            float4 v = make_float4(0.f, 0.f, 0.f, 0.f);
            if (gr < nrows) {
                if (SEL == 0)      v = Xext[gr * F4 + kk * 8 + c];
                else if (SEL == 1) v = g_xa[gr * F4 + kk * 8 + c];
                else               v = g_xb[gr * F4 + kk * 8 + c];
            }
            float* p = xs + r * XS_LD + c * 4;
            p[0] = v.x; p[1] = v.y; p[2] = v.z; p[3] = v.w;
        }
        __syncthreads();
        #pragma unroll
        for (int k = 0; k < 32; k++) {
            const float* wrow = ws + (kk * 32 + k) * WS_LD;
            float4 b0 = *(const float4*)(wrow + c0);
            float4 b1 = *(const float4*)(wrow + c0 + 64);
            #pragma unroll
            for (int j = 0; j < 8; j++) {
                float a = xs[(ty * 8 + j) * XS_LD + k];
                acc0[j].x += a * b0.x; acc0[j].y += a * b0.y;
                acc0[j].z += a * b0.z; acc0[j].w += a * b0.w;
                acc1[j].x += a * b1.x; acc1[j].y += a * b1.y;
                acc1[j].z += a * b1.z; acc1[j].w += a * b1.w;
            }
        }
        __syncthreads();
    }
    const int tx = c0 >> 2;
    #pragma unroll
    for (int j = 0; j < 8; j++) {
        int gr = row0 + ty * 8 + j;
        if (gr < nrows) {
            g_h[gr * F4 + tx]      = acc0[j];
            g_h[gr * F4 + tx + 16] = acc1[j];
        }
    }
}

// ---------------- aggregate + bias + L2 normalize + ReLU ----------------
// one warp per node; lane owns 4 contiguous features; gather unrolled x4 (MLP)
template<int SEL>
__global__ void agg_norm_relu_kernel(const float* __restrict__ bias,
                                     float4* __restrict__ OUText) {
    int node = (blockIdx.x * blockDim.x + threadIdx.x) >> 5;
    int lane = threadIdx.x & 31;
    if (node >= N_NODES) return;
    int s = g_off[node], e = g_off[node + 1];
    float4 acc = make_float4(0.f, 0.f, 0.f, 0.f);
    int i = s;
    for (; i + 3 < e; i += 4) {
        int u0 = g_srcs[i + 0];
        int u1 = g_srcs[i + 1];
        int u2 = g_srcs[i + 2];
        int u3 = g_srcs[i + 3];
        float4 v0 = g_h[u0 * F4 + lane];
        float4 v1 = g_h[u1 * F4 + lane];
        float4 v2 = g_h[u2 * F4 + lane];
        float4 v3 = g_h[u3 * F4 + lane];
        acc.x += v0.x + v1.x + v2.x + v3.x;
        acc.y += v0.y + v1.y + v2.y + v3.y;
        acc.z += v0.z + v1.z + v2.z + v3.z;
        acc.w += v0.w + v1.w + v2.w + v3.w;
    }
    for (; i < e; i++) {
        int u = g_srcs[i];
        float4 v = g_h[u * F4 + lane];
        acc.x += v.x; acc.y += v.y; acc.z += v.z; acc.w += v.w;
    }
    float4 b4 = ((const float4*)bias)[lane];
    acc.x += b4.x; acc.y += b4.y; acc.z += b4.z; acc.w += b4.w;
    float ss = acc.x * acc.x + acc.y * acc.y + acc.z * acc.z + acc.w * acc.w;
    #pragma unroll
    for (int off = 16; off > 0; off >>= 1)
        ss += __shfl_xor_sync(0xFFFFFFFFu, ss, off);
    float inv = 1.f / fmaxf(sqrtf(ss), 1e-12f);
    float4 r;
    r.x = fmaxf(acc.x * inv, 0.f);
    r.y = fmaxf(acc.y * inv, 0.f);
    r.z = fmaxf(acc.z * inv, 0.f);
    r.w = fmaxf(acc.w * inv, 0.f);
    if (SEL == 0)      OUText[node * F4 + lane] = r;
    else if (SEL == 1) g_xa[node * F4 + lane]   = r;
    else               g_xb[node * F4 + lane]   = r;
}

// ---------------- final linear + softmax ----------------
__global__ void final_kernel(const float* __restrict__ X4,
                             const float* __restrict__ Wl,
                             const float* __restrict__ bl,
                             float* __restrict__ logits,
                             float* __restrict__ probs) {
    __shared__ float xsh[32][129];
    __shared__ float wsh[F][NCLASS];
    __shared__ float lsh[32][NCLASS];
    __shared__ float mx[32], inv[32];
    int tid = threadIdx.x;
    int n0 = blockIdx.x * 32;

    for (int i = tid; i < 32 * F; i += 256) {
        int n = i >> 7, k = i & 127;
        int gn = n0 + n;
        xsh[n][k] = (gn < N_NODES) ? X4[gn * F + k] : 0.f;
    }
    for (int i = tid; i < F * NCLASS; i += 256)
        wsh[i / NCLASS][i % NCLASS] = Wl[i];
    __syncthreads();

    for (int idx = tid; idx < 32 * NCLASS; idx += 256) {
        int n = idx / NCLASS, c = idx % NCLASS;
        float s = bl[c];
        #pragma unroll
        for (int k = 0; k < F; k++) s += xsh[n][k] * wsh[k][c];
        lsh[n][c] = s;
    }
    __syncthreads();

    if (tid < 32) {
        float m = -1e30f;
        #pragma unroll
        for (int c = 0; c < NCLASS; c++) m = fmaxf(m, lsh[tid][c]);
        float sum = 0.f;
        #pragma unroll
        for (int c = 0; c < NCLASS; c++) sum += expf(lsh[tid][c] - m);
        mx[tid] = m; inv[tid] = 1.f / sum;
    }
    __syncthreads();

    for (int idx = tid; idx < 32 * NCLASS; idx += 256) {
        int n = idx / NCLASS, c = idx % NCLASS;
        int gn = n0 + n;
        if (gn < N_NODES) {
            float l = lsh[n][c];
            logits[gn * NCLASS + c] = l;
            probs[gn * NCLASS + c]  = expf(l - mx[n]) * inv[n];
        }
    }
}

// ---------------- launch ----------------
extern "C" void kernel_launch(void* const* d_in, const int* in_sizes, int n_in,
                              void* d_out, int out_size) {
    const float* x  = (const float*)d_in[0];
    const int*   ei = (const int*)d_in[1];   // int32 (2, 640000)
    const float* W1 = (const float*)d_in[2];
    const float* b1 = (const float*)d_in[3];
    const float* W2 = (const float*)d_in[4];
    const float* b2 = (const float*)d_in[5];
    const float* W3 = (const float*)d_in[6];
    const float* b3 = (const float*)d_in[7];
    const float* W4 = (const float*)d_in[8];
    const float* b4 = (const float*)d_in[9];
    const float* Wl = (const float*)d_in[10];
    const float* bl = (const float*)d_in[11];

    const int* src = ei;
    const int* dst = ei + N_EDGES;

    float* out    = (float*)d_out;
    float* logits = out;                          // 50000*40
    float* probs  = out + N_NODES * NCLASS;       // 50000*40
    float* x4out  = out + 2 * N_NODES * NCLASS;   // 50000*128

    const int T = 256;
    const int gemm_blocks = (N_NODES + 127) / 128;          // 391
    const int agg_blocks  = (N_NODES * 32 + T - 1) / T;     // 6250
    const int edge_blocks = (N_EDGES + T - 1) / T;          // 2500

    // opt-in to >48KB dynamic smem (idempotent, host-side only)
    cudaFuncSetAttribute(gemm128_kernel<0>, cudaFuncAttributeMaxDynamicSharedMemorySize, GEMM_SMEM);
    cudaFuncSetAttribute(gemm128_kernel<1>, cudaFuncAttributeMaxDynamicSharedMemorySize, GEMM_SMEM);
    cudaFuncSetAttribute(gemm128_kernel<2>, cudaFuncAttributeMaxDynamicSharedMemorySize, GEMM_SMEM);

    // Build CSR once per call (reused by all 4 layers)
    zero_cnt_kernel<<<(N_NODES + T - 1) / T, T>>>();
    hist_kernel<<<edge_blocks, T>>>(dst);
    scanA_kernel<<<SCAN_BLKS, 1024>>>();
    scanB_kernel<<<1, 64>>>();
    scanC_kernel<<<SCAN_BLKS, 1024>>>();
    fill_kernel<<<edge_blocks, T>>>(src, dst);

    // layer 1: x -> g_h -> g_xa
    gemm128_kernel<0><<<gemm_blocks, T, GEMM_SMEM>>>((const float4*)x, W1, N_NODES);
    agg_norm_relu_kernel<1><<<agg_blocks, T>>>(b1, nullptr);
    // layer 2: g_xa -> g_h -> g_xb
    gemm128_kernel<1><<<gemm_blocks, T, GEMM_SMEM>>>(nullptr, W2, N_NODES);
    agg_norm_relu_kernel<2><<<agg_blocks, T>>>(b2, nullptr);
    // layer 3: g_xb -> g_h -> g_xa
    gemm128_kernel<2><<<gemm_blocks, T, GEMM_SMEM>>>(nullptr, W3, N_NODES);
    agg_norm_relu_kernel<1><<<agg_blocks, T>>>(b3, nullptr);
    // layer 4: g_xa -> g_h -> x4out (external)
    gemm128_kernel<1><<<gemm_blocks, T, GEMM_SMEM>>>(nullptr, W4, N_NODES);
    agg_norm_relu_kernel<0><<<agg_blocks, T>>>(b4, (float4*)x4out);

    // head: logits + softmax
    final_kernel<<<(N_NODES + 31) / 32, T>>>(x4out, Wl, bl, logits, probs);
}